// round 9
// baseline (speedup 1.0000x reference)
#include <cuda_runtime.h>

#define EMBED 16
// tokens = 128 * 8192 = 1048576 (divides 256 exactly)

// History:
//   R5/R7: 39.4us — smem crossbar wall.
//   R8: weights in __constant__, 33.8us total (29.2 kernel + 4.6 memcpy nodes);
//       issue=70.3% -> instruction-issue bound (256 FFMA + 64 LDC / token).
//   R9: (a) packed fma.rn.f32x2 -> 128 FFMA2/token (halves FMA issues);
//       (b) prep kernel packs transposed weight pairs into __device__ scratch
//           (uniform LDG.128, L1-cached) -> no memcpy graph nodes.

// wp[e][j] = pack(w[2j][e], w[2j+1][e]); row e = 8 u64 = 4 x 16B
__device__ unsigned long long g_wp[EMBED * 8];

__global__ void prep_kernel(const float* __restrict__ w_out)
{
    int t = threadIdx.x;                  // 128 threads: t = e*8 + j
    if (t < EMBED * 8) {
        int e = t >> 3;
        int j = t & 7;
        float lo = w_out[(2 * j)     * EMBED + e];
        float hi = w_out[(2 * j + 1) * EMBED + e];
        unsigned long long p;
        asm("mov.b64 %0, {%1, %2};" : "=l"(p) : "f"(lo), "f"(hi));
        g_wp[t] = p;
    }
}

__global__ __launch_bounds__(256, 3)
void mhaq_kernel(const float* __restrict__ x,
                 const float* __restrict__ theta,
                 float* __restrict__ y)
{
    int token = blockIdx.x * blockDim.x + threadIdx.x;   // grid sized exactly

    const float4* xv = reinterpret_cast<const float4*>(x) + (size_t)token * 4;
    float*        yp = y + (size_t)token * EMBED;

    // 4 independent 128-bit loads -> MLP=4, coalesced 2048B/warp
    float4 a = xv[0];
    float4 b = xv[1];
    float4 c = xv[2];
    float4 d = xv[3];

    // theta: warp-uniform LDG.128, L1/L2-cached
    const float4* tv = reinterpret_cast<const float4*>(theta);
    float4 t0 = tv[0], t1 = tv[1], t2 = tv[2], t3 = tv[3];

    // phases (x + theta); consumed one-by-one in the e-loop
    float ph[EMBED] = {
        a.x + t0.x, a.y + t0.y, a.z + t0.z, a.w + t0.w,
        b.x + t1.x, b.y + t1.y, b.z + t1.z, b.w + t1.w,
        c.x + t2.x, c.y + t2.y, c.z + t2.z, c.w + t2.w,
        d.x + t3.x, d.y + t3.y, d.z + t3.z, d.w + t3.w };

    // packed accumulators: acc[j] lanes = outputs (2j, 2j+1)
    unsigned long long acc[8];

    const ulonglong2* wp = reinterpret_cast<const ulonglong2*>(g_wp);

    // e = 0: mul.rn.f32x2 init
    {
        float z = __cosf(ph[0]);
        unsigned long long z2;
        asm("mov.b64 %0, {%1, %1};" : "=l"(z2) : "f"(z));
        ulonglong2 p0 = wp[0], p1 = wp[1], p2 = wp[2], p3 = wp[3]; // row 0: 4x LDG.128
        asm("mul.rn.f32x2 %0, %1, %2;" : "=l"(acc[0]) : "l"(z2), "l"(p0.x));
        asm("mul.rn.f32x2 %0, %1, %2;" : "=l"(acc[1]) : "l"(z2), "l"(p0.y));
        asm("mul.rn.f32x2 %0, %1, %2;" : "=l"(acc[2]) : "l"(z2), "l"(p1.x));
        asm("mul.rn.f32x2 %0, %1, %2;" : "=l"(acc[3]) : "l"(z2), "l"(p1.y));
        asm("mul.rn.f32x2 %0, %1, %2;" : "=l"(acc[4]) : "l"(z2), "l"(p2.x));
        asm("mul.rn.f32x2 %0, %1, %2;" : "=l"(acc[5]) : "l"(z2), "l"(p2.y));
        asm("mul.rn.f32x2 %0, %1, %2;" : "=l"(acc[6]) : "l"(z2), "l"(p3.x));
        asm("mul.rn.f32x2 %0, %1, %2;" : "=l"(acc[7]) : "l"(z2), "l"(p3.y));
    }

    // e = 1..15: 4 uniform LDG.128 + 1 MUFU + 1 pack + 8 FFMA2 per e
    #pragma unroll
    for (int e = 1; e < EMBED; e++) {
        float z = __cosf(ph[e]);
        unsigned long long z2;
        asm("mov.b64 %0, {%1, %1};" : "=l"(z2) : "f"(z));
        ulonglong2 p0 = wp[e * 4 + 0];
        ulonglong2 p1 = wp[e * 4 + 1];
        ulonglong2 p2 = wp[e * 4 + 2];
        ulonglong2 p3 = wp[e * 4 + 3];
        asm("fma.rn.f32x2 %0, %1, %2, %0;" : "+l"(acc[0]) : "l"(z2), "l"(p0.x));
        asm("fma.rn.f32x2 %0, %1, %2, %0;" : "+l"(acc[1]) : "l"(z2), "l"(p0.y));
        asm("fma.rn.f32x2 %0, %1, %2, %0;" : "+l"(acc[2]) : "l"(z2), "l"(p1.x));
        asm("fma.rn.f32x2 %0, %1, %2, %0;" : "+l"(acc[3]) : "l"(z2), "l"(p1.y));
        asm("fma.rn.f32x2 %0, %1, %2, %0;" : "+l"(acc[4]) : "l"(z2), "l"(p2.x));
        asm("fma.rn.f32x2 %0, %1, %2, %0;" : "+l"(acc[5]) : "l"(z2), "l"(p2.y));
        asm("fma.rn.f32x2 %0, %1, %2, %0;" : "+l"(acc[6]) : "l"(z2), "l"(p3.x));
        asm("fma.rn.f32x2 %0, %1, %2, %0;" : "+l"(acc[7]) : "l"(z2), "l"(p3.y));
    }

    // acc[j] lanes are already (o=2j, o=2j+1): store pairs directly, 4x STG.128
    asm volatile("st.global.v2.b64 [%0], {%1, %2};" ::
                 "l"(yp + 0), "l"(acc[0]), "l"(acc[1]) : "memory");
    asm volatile("st.global.v2.b64 [%0], {%1, %2};" ::
                 "l"(yp + 4), "l"(acc[2]), "l"(acc[3]) : "memory");
    asm volatile("st.global.v2.b64 [%0], {%1, %2};" ::
                 "l"(yp + 8), "l"(acc[4]), "l"(acc[5]) : "memory");
    asm volatile("st.global.v2.b64 [%0], {%1, %2};" ::
                 "l"(yp + 12), "l"(acc[6]), "l"(acc[7]) : "memory");
}

extern "C" void kernel_launch(void* const* d_in, const int* in_sizes, int n_in,
                              void* d_out, int out_size)
{
    const float* x     = (const float*)d_in[0];   // [B, S, E]
    const float* theta = (const float*)d_in[1];   // [E]
    const float* w_out = (const float*)d_in[2];   // [E, E] row-major [o][e]
    float* y           = (float*)d_out;

    // Pack transposed weight pairs into device scratch (stream-ordered before main)
    prep_kernel<<<1, 128>>>(w_out);

    int n_tokens = in_sizes[0] / EMBED;           // 1048576, multiple of 256
    int threads = 256;
    int blocks = n_tokens / threads;              // 4096, exact
    mhaq_kernel<<<blocks, threads>>>(x, theta, y);
}

// round 10
// speedup vs baseline: 1.8862x; 1.8862x over previous
#include <cuda_runtime.h>

#define EMBED 16
// tokens = 128 * 8192 = 1048576 (divides 256 exactly)

// History:
//   R5/R7: 39.4us — smem crossbar wall (~8 wavefronts/token, width-invariant).
//   R8: weights in __constant__ (const port) -> 33.8us; issue=70.3% (issue-bound).
//   R9: weights via LDG from __device__ global -> 59.4us REGRESSION: LDG->LDG
//       structural floor 4 on the LSU path (L1=84%). f32x2 idea untested.
//   R10: f32x2 packed FMA *with* constant-port weights: prep kernel packs
//        pair-transposed weights -> staging -> ONE D2D memcpyToSymbol ->
//        128 FFMA2 + 64 LDC.128 per token (~250 issues vs ~390 in R8).

// c_wp2[e*4 + k] = { pack(w[4k][e],   w[4k+1][e]),
//                    pack(w[4k+2][e], w[4k+3][e]) }
__constant__ ulonglong2 c_wp2[EMBED * 4];
__device__ unsigned long long g_stage[EMBED * 8];

__global__ void prep_kernel(const float* __restrict__ w_out)
{
    int t = threadIdx.x;                  // 128 threads: t = e*8 + j
    if (t < EMBED * 8) {
        int e = t >> 3;
        int j = t & 7;                    // output pair index: lanes (2j, 2j+1)
        float lo = w_out[(2 * j)     * EMBED + e];
        float hi = w_out[(2 * j + 1) * EMBED + e];
        unsigned long long p;
        asm("mov.b64 %0, {%1, %2};" : "=l"(p) : "f"(lo), "f"(hi));
        g_stage[t] = p;
    }
}

__global__ __launch_bounds__(256, 3)
void mhaq_kernel(const float* __restrict__ x,
                 const float* __restrict__ theta,
                 float* __restrict__ y)
{
    int token = blockIdx.x * blockDim.x + threadIdx.x;   // grid sized exactly

    const float4* xv = reinterpret_cast<const float4*>(x) + (size_t)token * 4;
    float*        yp = y + (size_t)token * EMBED;

    // 4 independent 128-bit loads -> MLP=4, coalesced 2048B/warp
    float4 a = xv[0];
    float4 b = xv[1];
    float4 c = xv[2];
    float4 d = xv[3];

    // theta: 4 warp-uniform LDG.128 (tiny, L1/L2-cached)
    const float4* tv = reinterpret_cast<const float4*>(theta);
    float4 t0 = tv[0], t1 = tv[1], t2 = tv[2], t3 = tv[3];

    float ph[EMBED] = {
        a.x + t0.x, a.y + t0.y, a.z + t0.z, a.w + t0.w,
        b.x + t1.x, b.y + t1.y, b.z + t1.z, b.w + t1.w,
        c.x + t2.x, c.y + t2.y, c.z + t2.z, c.w + t2.w,
        d.x + t3.x, d.y + t3.y, d.z + t3.z, d.w + t3.w };

    // packed accumulators: acc[j] lanes = outputs (2j, 2j+1)
    unsigned long long acc[8];

    // e = 0: mul.rn.f32x2 init; 4x LDC.128 (const port) per e
    {
        float z = __cosf(ph[0]);
        unsigned long long z2;
        asm("mov.b64 %0, {%1, %1};" : "=l"(z2) : "f"(z));
        ulonglong2 p0 = c_wp2[0], p1 = c_wp2[1], p2 = c_wp2[2], p3 = c_wp2[3];
        asm("mul.rn.f32x2 %0, %1, %2;" : "=l"(acc[0]) : "l"(z2), "l"(p0.x));
        asm("mul.rn.f32x2 %0, %1, %2;" : "=l"(acc[1]) : "l"(z2), "l"(p0.y));
        asm("mul.rn.f32x2 %0, %1, %2;" : "=l"(acc[2]) : "l"(z2), "l"(p1.x));
        asm("mul.rn.f32x2 %0, %1, %2;" : "=l"(acc[3]) : "l"(z2), "l"(p1.y));
        asm("mul.rn.f32x2 %0, %1, %2;" : "=l"(acc[4]) : "l"(z2), "l"(p2.x));
        asm("mul.rn.f32x2 %0, %1, %2;" : "=l"(acc[5]) : "l"(z2), "l"(p2.y));
        asm("mul.rn.f32x2 %0, %1, %2;" : "=l"(acc[6]) : "l"(z2), "l"(p3.x));
        asm("mul.rn.f32x2 %0, %1, %2;" : "=l"(acc[7]) : "l"(z2), "l"(p3.y));
    }

    // e = 1..15: 1 MUFU + 1 pack + 4 LDC.128 + 8 FFMA2 per e
    #pragma unroll
    for (int e = 1; e < EMBED; e++) {
        float z = __cosf(ph[e]);
        unsigned long long z2;
        asm("mov.b64 %0, {%1, %1};" : "=l"(z2) : "f"(z));
        ulonglong2 p0 = c_wp2[e * 4 + 0];
        ulonglong2 p1 = c_wp2[e * 4 + 1];
        ulonglong2 p2 = c_wp2[e * 4 + 2];
        ulonglong2 p3 = c_wp2[e * 4 + 3];
        asm("fma.rn.f32x2 %0, %1, %2, %0;" : "+l"(acc[0]) : "l"(z2), "l"(p0.x));
        asm("fma.rn.f32x2 %0, %1, %2, %0;" : "+l"(acc[1]) : "l"(z2), "l"(p0.y));
        asm("fma.rn.f32x2 %0, %1, %2, %0;" : "+l"(acc[2]) : "l"(z2), "l"(p1.x));
        asm("fma.rn.f32x2 %0, %1, %2, %0;" : "+l"(acc[3]) : "l"(z2), "l"(p1.y));
        asm("fma.rn.f32x2 %0, %1, %2, %0;" : "+l"(acc[4]) : "l"(z2), "l"(p2.x));
        asm("fma.rn.f32x2 %0, %1, %2, %0;" : "+l"(acc[5]) : "l"(z2), "l"(p2.y));
        asm("fma.rn.f32x2 %0, %1, %2, %0;" : "+l"(acc[6]) : "l"(z2), "l"(p3.x));
        asm("fma.rn.f32x2 %0, %1, %2, %0;" : "+l"(acc[7]) : "l"(z2), "l"(p3.y));
    }

    // acc[j] lanes are already (o=2j, o=2j+1): 4x STG.128
    asm volatile("st.global.v2.b64 [%0], {%1, %2};" ::
                 "l"(yp + 0), "l"(acc[0]), "l"(acc[1]) : "memory");
    asm volatile("st.global.v2.b64 [%0], {%1, %2};" ::
                 "l"(yp + 4), "l"(acc[2]), "l"(acc[3]) : "memory");
    asm volatile("st.global.v2.b64 [%0], {%1, %2};" ::
                 "l"(yp + 8), "l"(acc[4]), "l"(acc[5]) : "memory");
    asm volatile("st.global.v2.b64 [%0], {%1, %2};" ::
                 "l"(yp + 12), "l"(acc[6]), "l"(acc[7]) : "memory");
}

extern "C" void kernel_launch(void* const* d_in, const int* in_sizes, int n_in,
                              void* d_out, int out_size)
{
    const float* x     = (const float*)d_in[0];   // [B, S, E]
    const float* theta = (const float*)d_in[1];   // [E]
    const float* w_out = (const float*)d_in[2];   // [E, E] row-major [o][e]
    float* y           = (float*)d_out;

    // 1) pack pair-transposed weights into device staging (kernel launch)
    prep_kernel<<<1, 128>>>(w_out);

    // 2) ONE async D2D copy staging -> __constant__ (graph-capturable)
    void* stage_ptr = nullptr;
    cudaGetSymbolAddress(&stage_ptr, g_stage);    // host-side query, no stream op
    cudaMemcpyToSymbolAsync(c_wp2, stage_ptr, EMBED * 8 * sizeof(unsigned long long),
                            0, cudaMemcpyDeviceToDevice, 0);

    // 3) main kernel
    int n_tokens = in_sizes[0] / EMBED;           // 1048576, multiple of 256
    int threads = 256;
    int blocks = n_tokens / threads;              // 4096, exact
    mhaq_kernel<<<blocks, threads>>>(x, theta, y);
}